// round 2
// baseline (speedup 1.0000x reference)
#include <cuda_runtime.h>
#include <cstdint>
#include <cstddef>

// ---------------------------------------------------------------------------
// NonLocalMSA: x[16,64,256,256] -> qkv 1x1 -> dw3x3 -> window MSA -> proj 1x1
// Windows 8x8 of 32x32, heads=8, head_dim = 4*32*64 = 8192.
// head h of a window owns window-rows 4h..4h+3 (head = b0_local/4).
//
// NOTE on head-dim ordering: the reference flattens head-dim as (b0r,b1,c);
// our gather uses the bijection d -> (b0r, c, b1) instead. Since q, k, v and
// the output scatter all use the SAME bijection, and QK^T / attn@V are
// invariant under a consistent permutation of the contracted head dimension,
// every output memory location still receives the reference value. The
// permuted order makes the inner 32 d-indices contiguous in x (b1-contiguous),
// giving 128B-aligned coalesced gathers.
// ---------------------------------------------------------------------------

#define HW      65536     // 256*256
#define BATCH   16
#define CIN     64
#define C3      192
#define HEADS   8
#define NTOK    64        // windows per image

// scratch (static __device__ globals: the sanctioned no-alloc workaround)
// g_buf is reused: phase 1 holds pointwise qkv output (805 MB, dead after
// k_dw), phase 2's first 268 MB hold the attention output read by k_proj.
__device__ float g_buf [BATCH * C3 * HW];   // 805 MB (dual purpose)
__device__ float g_qkv2[BATCH * C3 * HW];   // after depthwise (805 MB)
__device__ float g_attnw[BATCH * HEADS * NTOK * NTOK];  // softmax(attn) (2 MB)

// ---------------------------------------------------------------------------
// K1: pointwise qkv GEMM.  C[o,p] = sum_c W[o,c] * X[c,p] per batch.
// Block: 64 o x 256 p tile, 256 threads, each thread 8x8 register tile.
// ---------------------------------------------------------------------------
__global__ __launch_bounds__(256) void k_pointwise(const float* __restrict__ x,
                                                   const float* __restrict__ w)
{
    const int b     = blockIdx.z;
    const int oBase = blockIdx.y * 64;        // 0,64,128
    const int pBase = blockIdx.x * 256;

    __shared__ float Ws[64 * 64];             // [o][c]
    __shared__ float Xs[16 * 256];            // [cc][p]

    const int t  = threadIdx.x;
    const int tx = t & 31;                    // pixel lane
    const int ty = t >> 5;                    // o lane

    #pragma unroll
    for (int i = 0; i < 16; i++)
        Ws[t + i * 256] = w[oBase * 64 + t + i * 256];

    float acc[8][8];
    #pragma unroll
    for (int i = 0; i < 8; i++)
        #pragma unroll
        for (int j = 0; j < 8; j++) acc[i][j] = 0.f;

    const float* xb = x + (size_t)b * CIN * HW + pBase;

    for (int cb = 0; cb < 64; cb += 16) {
        __syncthreads();
        #pragma unroll
        for (int k = 0; k < 4; k++) {
            int idx = t + k * 256;            // float4 id, 1024 total
            int cc  = idx >> 6;               // 64 float4 per 256-pixel row
            int pp  = (idx & 63) << 2;
            float4 v = *(const float4*)(xb + (size_t)(cb + cc) * HW + pp);
            *(float4*)(&Xs[cc * 256 + pp]) = v;
        }
        __syncthreads();
        #pragma unroll
        for (int cc = 0; cc < 16; cc++) {
            float xr[8], wr[8];
            #pragma unroll
            for (int j = 0; j < 8; j++) xr[j] = Xs[cc * 256 + tx + j * 32];
            #pragma unroll
            for (int i = 0; i < 8; i++) wr[i] = Ws[(ty + i * 8) * 64 + cb + cc];
            #pragma unroll
            for (int i = 0; i < 8; i++)
                #pragma unroll
                for (int j = 0; j < 8; j++) acc[i][j] += wr[i] * xr[j];
        }
    }

    float* ob = g_buf + ((size_t)b * C3 + oBase) * HW + pBase;
    #pragma unroll
    for (int i = 0; i < 8; i++)
        #pragma unroll
        for (int j = 0; j < 8; j++)
            ob[(size_t)(ty + i * 8) * HW + tx + j * 32] = acc[i][j];
}

// ---------------------------------------------------------------------------
// K2: 3x3 depthwise conv, pad 1. 32x32 output tile per block, 256 threads,
// 4 outputs/thread (consecutive rows). Halo overhead 34^2/32^2 = 13%.
// ---------------------------------------------------------------------------
__global__ __launch_bounds__(256) void k_dw(const float* __restrict__ wdw)
{
    __shared__ float tile[34][36];            // +2 col pad
    const int bc = blockIdx.z;                // b*192 + ch
    const int ch = bc % 192;
    const int y0 = blockIdx.y * 32;
    const int x0 = blockIdx.x * 32;
    const int t  = threadIdx.x;

    const float* in = g_buf + (size_t)bc * HW;

    for (int i = t; i < 34 * 34; i += 256) {
        int yy = i / 34, xx = i - yy * 34;
        int gy = y0 + yy - 1, gx = x0 + xx - 1;
        float v = 0.f;
        if (gy >= 0 && gy < 256 && gx >= 0 && gx < 256)
            v = in[gy * 256 + gx];
        tile[yy][xx] = v;
    }

    float wv[9];
    #pragma unroll
    for (int k = 0; k < 9; k++) wv[k] = wdw[ch * 9 + k];

    __syncthreads();

    const int tx = t & 31;
    const int ty = (t >> 5) * 4;              // 4 consecutive rows per thread
    float* ob = g_qkv2 + (size_t)bc * HW + (size_t)(y0 + ty) * 256 + x0 + tx;

    #pragma unroll
    for (int r = 0; r < 4; r++) {
        float s = 0.f;
        #pragma unroll
        for (int dy = 0; dy < 3; dy++)
            #pragma unroll
            for (int dx = 0; dx < 3; dx++)
                s += wv[dy * 3 + dx] * tile[ty + r + dy][tx + dx];
        ob[r * 256] = s;
    }
}

// gather offset (within one batch's 192*HW block, before qkv-channel offset)
// idx = tok*64 + d (d = local index in 64-wide chunk of head dim)
__device__ __forceinline__ size_t qkv_off(int idx, int chunk, int h)
{
    int d    = idx & 63;
    int tok  = idx >> 6;
    int seg  = chunk * 2 + (d >> 5);          // seg = b0r*64 + c
    int b0r  = seg >> 6;
    int c    = seg & 63;
    int row  = ((tok >> 3) << 5) + (h << 2) + b0r;
    int col  = ((tok & 7) << 5) + (d & 31);
    return ((size_t)c << 16) + (size_t)((row << 8) + col);
}

// ---------------------------------------------------------------------------
// K3: sim = scale*q.k^T + pos, softmax -> g_attnw.  One block per (b,h).
// Streams head-dim in 64-wide chunks; 256 threads, 4x4 tile each.
// Row softmax done with 16-lane butterfly shuffles (tj spans lanes 0..15).
// ---------------------------------------------------------------------------
__global__ __launch_bounds__(256) void k_sim(const float* __restrict__ pos)
{
    const int bh = blockIdx.x;
    const int b  = bh >> 3;
    const int h  = bh & 7;

    __shared__ float qs[64 * 65];
    __shared__ float ks[64 * 65];

    const int t  = threadIdx.x;
    const int tj = t & 15;                    // j group
    const int ti = t >> 4;                    // i group

    const size_t bbase = (size_t)b * C3 * HW;
    const float* src   = g_qkv2 + bbase;

    float acc[4][4];
    #pragma unroll
    for (int i = 0; i < 4; i++)
        #pragma unroll
        for (int j = 0; j < 4; j++) acc[i][j] = 0.f;

    for (int chunk = 0; chunk < 128; chunk++) {
        __syncthreads();
        #pragma unroll
        for (int k = 0; k < 16; k++) {
            int idx = t + k * 256;            // 0..4095 : tok*64 + d
            size_t off = qkv_off(idx, chunk, h);
            int tok = idx >> 6, d = idx & 63;
            qs[tok * 65 + d] = src[off];                       // q : ch c
            ks[tok * 65 + d] = src[((size_t)64 << 16) + off];  // k : ch 64+c
        }
        __syncthreads();
        #pragma unroll 8
        for (int dk = 0; dk < 64; dk++) {
            float qr[4], kr[4];
            #pragma unroll
            for (int ii = 0; ii < 4; ii++) qr[ii] = qs[(ti * 4 + ii) * 65 + dk];
            #pragma unroll
            for (int jj = 0; jj < 4; jj++) kr[jj] = ks[(tj * 4 + jj) * 65 + dk];
            #pragma unroll
            for (int ii = 0; ii < 4; ii++)
                #pragma unroll
                for (int jj = 0; jj < 4; jj++) acc[ii][jj] += qr[ii] * kr[jj];
        }
    }

    // softmax over j (rows of 64, split across 16 tj lanes * 4 jj)
    const float scale = 0.011048543456039806f;   // 8192^-0.5
    #pragma unroll
    for (int ii = 0; ii < 4; ii++) {
        const int i = ti * 4 + ii;
        const float* pr = pos + ((size_t)(h * 64 + i) << 6);
        float s[4];
        float m = -1e30f;
        #pragma unroll
        for (int jj = 0; jj < 4; jj++) {
            s[jj] = acc[ii][jj] * scale + pr[tj * 4 + jj];
            m = fmaxf(m, s[jj]);
        }
        #pragma unroll
        for (int off = 1; off < 16; off <<= 1)
            m = fmaxf(m, __shfl_xor_sync(0xffffffffu, m, off));
        float e[4], sum = 0.f;
        #pragma unroll
        for (int jj = 0; jj < 4; jj++) { e[jj] = expf(s[jj] - m); sum += e[jj]; }
        #pragma unroll
        for (int off = 1; off < 16; off <<= 1)
            sum += __shfl_xor_sync(0xffffffffu, sum, off);
        float inv = 1.f / sum;
        float4 v4 = make_float4(e[0] * inv, e[1] * inv, e[2] * inv, e[3] * inv);
        *(float4*)(g_attnw + ((size_t)(bh * 64 + i) << 6) + tj * 4) = v4;
    }
}

// ---------------------------------------------------------------------------
// K4: out = attn @ v, scattered back to spatial layout in g_buf (reused).
// Split 4-ways over head-dim chunks: grid = 16*8*4 = 512 blocks.
// ---------------------------------------------------------------------------
__global__ __launch_bounds__(256) void k_av()
{
    const int blk  = blockIdx.x;
    const int part = blk & 3;
    const int bh   = blk >> 2;
    const int b    = bh >> 3;
    const int h    = bh & 7;

    __shared__ float as[64 * 65];             // attn
    __shared__ float vs[64 * 65];             // v chunk

    const int t  = threadIdx.x;
    const int td = t & 15;                    // dk group (4 consecutive d)
    const int ti = t >> 4;                    // i group

    // load attn once
    #pragma unroll
    for (int k = 0; k < 16; k++) {
        int idx = t + k * 256;
        int i = idx >> 6, j = idx & 63;
        as[i * 65 + j] = g_attnw[(size_t)bh * 4096 + idx];
    }

    const size_t bbase = (size_t)b * C3 * HW;
    const float* vsrc  = g_qkv2 + bbase + ((size_t)128 << 16);
    float* outb        = g_buf + (size_t)b * CIN * HW;   // reuse phase-1 buffer

    for (int cc = 0; cc < 32; cc++) {
        const int chunk = part * 32 + cc;
        __syncthreads();
        #pragma unroll
        for (int k = 0; k < 16; k++) {
            int idx = t + k * 256;
            int tok = idx >> 6, d = idx & 63;
            vs[tok * 65 + d] = vsrc[qkv_off(idx, chunk, h)];
        }
        __syncthreads();

        float ao[4][4];
        #pragma unroll
        for (int i = 0; i < 4; i++)
            #pragma unroll
            for (int j = 0; j < 4; j++) ao[i][j] = 0.f;

        #pragma unroll 8
        for (int j = 0; j < 64; j++) {
            float ar[4], vr[4];
            #pragma unroll
            for (int ii = 0; ii < 4; ii++) ar[ii] = as[(ti * 4 + ii) * 65 + j];
            #pragma unroll
            for (int dd = 0; dd < 4; dd++) vr[dd] = vs[j * 65 + td * 4 + dd];
            #pragma unroll
            for (int ii = 0; ii < 4; ii++)
                #pragma unroll
                for (int dd = 0; dd < 4; dd++) ao[ii][dd] += ar[ii] * vr[dd];
        }

        // scatter: thread's 4 d are consecutive -> float4 stores
        const int s   = td >> 3;
        const int b1  = (td * 4) & 31;
        const int seg = chunk * 2 + s;
        const int b0r = seg >> 6;
        const int c   = seg & 63;
        #pragma unroll
        for (int ii = 0; ii < 4; ii++) {
            int tok = ti * 4 + ii;
            int row = ((tok >> 3) << 5) + (h << 2) + b0r;
            int col = ((tok & 7) << 5) + b1;
            float4 v4 = make_float4(ao[ii][0], ao[ii][1], ao[ii][2], ao[ii][3]);
            *(float4*)(outb + ((size_t)c << 16) + (size_t)(row << 8) + col) = v4;
        }
    }
}

// ---------------------------------------------------------------------------
// K5: final 1x1 projection + bias -> d_out.
// ---------------------------------------------------------------------------
__global__ __launch_bounds__(256) void k_proj(const float* __restrict__ w,
                                              const float* __restrict__ bias,
                                              float* __restrict__ out)
{
    const int b     = blockIdx.z;
    const int pBase = blockIdx.x * 256;

    __shared__ float Ws[64 * 64];
    __shared__ float Xs[16 * 256];
    __shared__ float Bs[64];

    const int t  = threadIdx.x;
    const int tx = t & 31;
    const int ty = t >> 5;

    #pragma unroll
    for (int i = 0; i < 16; i++)
        Ws[t + i * 256] = w[t + i * 256];
    if (t < 64) Bs[t] = bias[t];

    float acc[8][8];
    #pragma unroll
    for (int i = 0; i < 8; i++)
        #pragma unroll
        for (int j = 0; j < 8; j++) acc[i][j] = 0.f;

    const float* xb = g_buf + (size_t)b * CIN * HW + pBase;

    for (int cb = 0; cb < 64; cb += 16) {
        __syncthreads();
        #pragma unroll
        for (int k = 0; k < 4; k++) {
            int idx = t + k * 256;
            int cc  = idx >> 6;
            int pp  = (idx & 63) << 2;
            float4 v = *(const float4*)(xb + (size_t)(cb + cc) * HW + pp);
            *(float4*)(&Xs[cc * 256 + pp]) = v;
        }
        __syncthreads();
        #pragma unroll
        for (int cc = 0; cc < 16; cc++) {
            float xr[8], wr[8];
            #pragma unroll
            for (int j = 0; j < 8; j++) xr[j] = Xs[cc * 256 + tx + j * 32];
            #pragma unroll
            for (int i = 0; i < 8; i++) wr[i] = Ws[(ty + i * 8) * 64 + cb + cc];
            #pragma unroll
            for (int i = 0; i < 8; i++)
                #pragma unroll
                for (int j = 0; j < 8; j++) acc[i][j] += wr[i] * xr[j];
        }
    }

    float* ob = out + (size_t)b * CIN * HW + pBase;
    #pragma unroll
    for (int i = 0; i < 8; i++) {
        float bb = Bs[ty + i * 8];
        #pragma unroll
        for (int j = 0; j < 8; j++)
            ob[(size_t)(ty + i * 8) * HW + tx + j * 32] = acc[i][j] + bb;
    }
}

// ---------------------------------------------------------------------------
extern "C" void kernel_launch(void* const* d_in, const int* in_sizes, int n_in,
                              void* d_out, int out_size)
{
    const float* x      = (const float*)d_in[0];
    const float* w_qkv  = (const float*)d_in[1];
    const float* w_dw   = (const float*)d_in[2];
    const float* w_proj = (const float*)d_in[3];
    const float* b_proj = (const float*)d_in[4];
    const float* pos    = (const float*)d_in[5];
    float* out = (float*)d_out;

    k_pointwise<<<dim3(256, 3, BATCH), 256>>>(x, w_qkv);
    k_dw<<<dim3(8, 8, BATCH * C3), 256>>>(w_dw);
    k_sim<<<BATCH * HEADS, 256>>>(pos);
    k_av<<<BATCH * HEADS * 4, 256>>>();
    k_proj<<<dim3(256, 1, BATCH), 256>>>(w_proj, b_proj, out);
}